// round 17
// baseline (speedup 1.0000x reference)
#include <cuda_runtime.h>
#include <cuda_fp16.h>
#include <cstdint>
#include <math.h>

#define BB 128
#define TT 1024
#define HH 512
#define NCTA 99
#define NTHR 512
#define RING 4

// smem: 3 A-buffers (128 rows x 272B) + persistent W (max 48 x 2064B)
#define ABYTES 34816
#define OFF_W  (3 * ABYTES)                // 104448
#define SMEM_BYTES (OFF_W + 48 * 2064)     // 203520

// ------------------------- persistent device state ---------------------------
__device__ float g_ig0[65 * 1536];                        // layer0 igates + bias
__device__ __align__(16) __half g_hA[3][RING][BB * HH];   // fp16 h ring [lay][slot]
__device__ __align__(16) __half g_wf16s[6][1536 * 512];   // fp16 weights [part]
__device__ unsigned g_prod[3];   // 32 * steps completed per layer
__device__ unsigned g_cons[3];   // external consumptions of layer l's output

// ------------------------------ helpers --------------------------------------
__device__ __forceinline__ float sigm(float x) { return 1.f / (1.f + __expf(-x)); }
__device__ __forceinline__ uint32_t smem_u32(const void* p) {
    uint32_t a;
    asm("{ .reg .u64 t; cvta.to.shared.u64 t, %1; cvt.u32.u64 %0, t; }" : "=r"(a) : "l"(p));
    return a;
}
__device__ __forceinline__ void ldsm4(uint32_t a, uint32_t& r0, uint32_t& r1,
                                      uint32_t& r2, uint32_t& r3) {
    asm volatile("ldmatrix.sync.aligned.m8n8.x4.shared.b16 {%0,%1,%2,%3}, [%4];"
                 : "=r"(r0), "=r"(r1), "=r"(r2), "=r"(r3) : "r"(a));
}
__device__ __forceinline__ void ldsm2(uint32_t a, uint32_t& r0, uint32_t& r1) {
    asm volatile("ldmatrix.sync.aligned.m8n8.x2.shared.b16 {%0,%1}, [%2];"
                 : "=r"(r0), "=r"(r1) : "r"(a));
}
__device__ __forceinline__ void mma4(float* d, uint32_t a0, uint32_t a1, uint32_t a2,
                                     uint32_t a3, uint32_t b0, uint32_t b1) {
    asm volatile("mma.sync.aligned.m16n8k16.row.col.f32.f16.f16.f32 "
                 "{%0,%1,%2,%3},{%4,%5,%6,%7},{%8,%9},{%0,%1,%2,%3};"
                 : "+f"(d[0]), "+f"(d[1]), "+f"(d[2]), "+f"(d[3])
                 : "r"(a0), "r"(a1), "r"(a2), "r"(a3), "r"(b0), "r"(b1));
}
__device__ __forceinline__ void cp16(uint32_t dst, const void* src) {
    asm volatile("cp.async.cg.shared.global [%0], [%1], 16;" :: "r"(dst), "l"(src));
}
#define CP_COMMIT() asm volatile("cp.async.commit_group;" ::: "memory")
#define CP_WAIT1()  asm volatile("cp.async.wait_group 1;" ::: "memory")
#define CP_WAIT0()  asm volatile("cp.async.wait_group 0;" ::: "memory")

// thread-0 poll until *p >= target, then block-wide release
__device__ __forceinline__ void wait_ge(volatile unsigned* p, unsigned target, int tid) {
    if (tid == 0) {
        while (*p < target) { }
    }
    __syncthreads();
}

// ------------------------------ prep kernels ---------------------------------
__global__ void k_zero() {
    long i = (long)blockIdx.x * blockDim.x + threadIdx.x;
    __half* ph = &g_hA[0][0][0];
    long nh = 3L * RING * BB * HH;
    for (long j = i; j < nh; j += (long)gridDim.x * blockDim.x) ph[j] = __float2half(0.f);
    if (i < 3) { g_prod[i] = 0u; g_cons[i] = 0u; }
}

__global__ void k_ig0(const float* __restrict__ emb, const float* __restrict__ w_ih,
                      const float* __restrict__ bias) {
    int idx = blockIdx.x * blockDim.x + threadIdx.x;
    if (idx >= 65 * 1536) return;
    int tok = idx / 1536, j = idx - tok * 1536;
    const float* e = emb + tok * HH;
    const float* w = w_ih + (long)j * HH;
    float acc = bias[j];
    #pragma unroll 8
    for (int k = 0; k < HH; ++k) acc += e[k] * w[k];
    g_ig0[idx] = acc;
}

__global__ void k_prepw(const float* __restrict__ w_ih, const float* __restrict__ w_hh,
                        const float* __restrict__ w_out) {
    long idx = (long)blockIdx.x * 256 + threadIdx.x;     // 6 * 1536 * 512
    if (idx >= 6L * 1536 * 512) return;
    int k = (int)(idx & 511);
    long r = idx >> 9;
    int row = (int)(r % 1536);
    int part = (int)(r / 1536);
    float v = 0.f;
    if (part == 0)      v = w_hh[(long)row * 512 + k];
    else if (part == 1) v = w_ih[(1536L + row) * 512 + k];
    else if (part == 2) v = w_hh[(1536L + row) * 512 + k];
    else if (part == 3) v = w_ih[(2L * 1536 + row) * 512 + k];
    else if (part == 4) v = w_hh[(2L * 1536 + row) * 512 + k];
    else if (row < 65)  v = w_out[(long)row * 512 + k];
    g_wf16s[part][(long)row * 512 + k] = __float2half(v);
}

// ------------------------------ GEMM core ------------------------------------
// Fused pipeline over NH halves of 4 chunks (K=128 each). Half 0 reads A0 with
// W column block kcol0; half 1 reads A1/kcol1. For NH=2, thread 0 polls waitp
// at j==2, just before chunk 4 is staged — the inter-layer wait hides behind
// the compute of half-0 chunks. Accumulates into acc[half].
// MODE 0: layer CTA (wg rows wg*24: r/z via x4, n via x2) -> 3 gate tiles
// MODE 1: out CTA wg0 (rows 0-15 via x4) -> tiles 0,1
// MODE 2: out CTA wg1 (rows 16-23 via x2) -> tile 2
template <int MODE, int NH>
__device__ __forceinline__ void gemm_run(
    const __half* __restrict__ A0, const __half* __restrict__ A1,
    uint32_t kcol0, uint32_t kcol1,
    uint32_t wbase, uint32_t pitchWB, uint32_t sbuf, int choff,
    volatile unsigned* waitp, unsigned waittgt,
    float (&acc)[2][3][4], int tid, int wg)
{
    const int lane = tid & 31, warp8 = (tid >> 5) & 7;
    const int lr = lane & 7, gq = lane >> 3;
    const uint32_t aoff = (uint32_t)((warp8 * 16 + lr + (gq & 1) * 8) * 272
                                     + (gq >> 1) * 16);
    const int wrowbase = (MODE == 0) ? wg * 24 : 0;
    const uint32_t w4row = (uint32_t)(wrowbase + lr + (gq & 1) * 8) * pitchWB;
    const uint32_t w2row = (uint32_t)(wrowbase + 16 + lr) * pitchWB;
    const uint32_t k4sub = (uint32_t)((gq >> 1) * 8) * 2;
    const uint32_t k2sub = (uint32_t)(((lane >> 3) & 1) * 8) * 2;
    const int TOT = NH * 4;

    auto stage = [&](int j) {
        const int half = j >> 2;
        const int cg = (j + choff) & 3;
        const __half* s0 = (half ? A1 : A0) + cg * 128;
        uint32_t buf = sbuf + (uint32_t)(j % 3) * ABYTES;
        #pragma unroll
        for (int i = 0; i < 4; ++i) {
            int e = tid + i * NTHR;
            int rr = e >> 4, u = e & 15;
            cp16(buf + (uint32_t)(rr * 272 + u * 16), s0 + (long)rr * HH + u * 8);
        }
        CP_COMMIT();
    };

    stage(0); stage(1);
    #pragma unroll 1
    for (int j = 0; j < TOT; ++j) {
        if (j == TOT - 1) CP_WAIT0(); else CP_WAIT1();
        if (NH == 2 && j == 2 && tid == 0) {
            while (*waitp < waittgt) { }           // gate staging of half-1 A
        }
        __syncthreads();
        if (j + 2 < TOT) stage(j + 2);
        const int half = j >> 2;
        const int cg = (j + choff) & 3;
        const uint32_t kbase = (half ? kcol1 : kcol0) + (uint32_t)cg * 256;
        const uint32_t buf = sbuf + (uint32_t)(j % 3) * ABYTES;
        float (*ac)[4] = acc[half];
        #pragma unroll
        for (int ks = 0; ks < 8; ++ks) {
            uint32_t a0, a1, a2, a3;
            ldsm4(buf + aoff + ks * 32, a0, a1, a2, a3);
            const uint32_t kk = kbase + ks * 32;
            if (MODE == 0) {
                uint32_t h0, h1, h2, h3, h4v, h5;
                ldsm4(wbase + w4row + kk + k4sub, h0, h1, h2, h3);
                ldsm2(wbase + w2row + kk + k2sub, h4v, h5);
                mma4(ac[0], a0, a1, a2, a3, h0, h2);
                mma4(ac[1], a0, a1, a2, a3, h1, h3);
                mma4(ac[2], a0, a1, a2, a3, h4v, h5);
            } else if (MODE == 1) {
                uint32_t h0, h1, h2, h3;
                ldsm4(wbase + w4row + kk + k4sub, h0, h1, h2, h3);
                mma4(ac[0], a0, a1, a2, a3, h0, h2);
                mma4(ac[1], a0, a1, a2, a3, h1, h3);
            } else {
                uint32_t h4v, h5;
                ldsm2(wbase + w2row + kk + k2sub, h4v, h5);
                mma4(ac[2], a0, a1, a2, a3, h4v, h5);
            }
        }
    }
    __syncthreads();
}

// ------------------------------- main kernel ---------------------------------
__global__ void __launch_bounds__(NTHR, 1) k_main(
    const int* __restrict__ x_seq,
    const float* __restrict__ bias, const float* __restrict__ b_n,
    const float* __restrict__ b_out, float* __restrict__ out)
{
    extern __shared__ unsigned char smem[];
    const uint32_t sbuf = smem_u32(smem);
    const uint32_t wbase = sbuf + OFF_W;
    const int tid = threadIdx.x;
    const int wg = tid >> 8;
    const int lane = tid & 31, warp8 = (tid >> 5) & 7;
    const int cta = blockIdx.x;

    // ---- role decode: 32 L0 | 32 L1 | 32 L2 | 3 out ----
    int role, lay = 0, n0 = 0, vbase = 0, rows_used, ktot, p0, p1;
    if (cta < 32) {
        role = 0; lay = 0; n0 = cta * 16; rows_used = 48; ktot = 512; p0 = 0; p1 = 0;
    } else if (cta < 64) {
        role = 1; lay = 1; n0 = (cta - 32) * 16; rows_used = 48; ktot = 1024; p0 = 1; p1 = 2;
    } else if (cta < 96) {
        role = 2; lay = 2; n0 = (cta - 64) * 16; rows_used = 48; ktot = 1024; p0 = 3; p1 = 4;
    } else {
        role = 3; lay = 3; vbase = (cta - 96) * 24; rows_used = 24; ktot = 512; p0 = 5; p1 = 5;
    }
    const int pitchWE = ktot + 8;
    const uint32_t pitchWB = (uint32_t)pitchWE * 2;
    const int choff = (cta * 5) & 3;
    const unsigned consC = (lay == 2) ? 3u : 32u;

    // ---- persistent W load (once) ----
    {
        __half* ws = (__half*)(smem + OFF_W);
        for (int e = tid; e < rows_used * ktot; e += NTHR) {
            int r = e / ktot, k = e - r * ktot;
            int grow;
            if (role < 3) {
                int blk = r >> 3, w = blk / 3, gate = blk % 3;
                grow = gate * HH + n0 + w * 8 + (r & 7);
            } else {
                grow = vbase + r;
                if (grow > 64) grow = 0;
            }
            int part = (k < 512) ? p0 : p1;
            ws[r * pitchWE + k] = g_wf16s[part][(long)grow * 512 + (k & 511)];
        }
    }
    __syncthreads();

    // ---- register-resident hidden state ----
    float hreg[4] = {0.f, 0.f, 0.f, 0.f};
    const int b0 = warp8 * 16 + (lane >> 2);
    const int g0 = n0 + wg * 8 + (lane & 3) * 2;

    for (int t = 0; t < TT; ++t) {
        const int wrs = t & (RING - 1);           // write slot
        const int rds = (t - 1) & (RING - 1);     // own previous slot

        if (role == 0) {
            wait_ge(&g_prod[0], 32u * (unsigned)t, tid);
            float acc[2][3][4] = {};
            gemm_run<0, 1>(g_hA[0][rds], g_hA[0][rds], 0, 0,
                           wbase, pitchWB, sbuf, choff, 0, 0, acc, tid, wg);
            if (t >= RING) wait_ge(&g_cons[0], 32u * (unsigned)(t - 3), tid);
            __half* slab = g_hA[0][wrs];
            #pragma unroll
            for (int bs = 0; bs < 2; ++bs) {
                const int b = b0 + 8 * bs;
                const int tok = __ldg(x_seq + (long)b * TT + t);
                const float* ig = g_ig0 + (long)tok * 1536;
                float hh[2];
                #pragma unroll
                for (int d = 0; d < 2; ++d) {
                    const int g = g0 + d, idx = bs * 2 + d;
                    float r = sigm(__ldg(ig + g) + acc[0][0][idx]);
                    float z = sigm(__ldg(ig + 512 + g) + acc[0][1][idx]);
                    float n = tanhf(__ldg(ig + 1024 + g)
                                    + r * (acc[0][2][idx] + __ldg(b_n + g)));
                    float h = n + z * (hreg[idx] - n);
                    hreg[idx] = h; hh[d] = h;
                }
                __half2 hv; hv.x = __float2half(hh[0]); hv.y = __float2half(hh[1]);
                *(__half2*)(slab + (long)b * HH + g0) = hv;
            }
            __threadfence();
            __syncthreads();
            if (tid == 0) atomicAdd(&g_prod[0], 1u);
        } else if (role == 1 || role == 2) {
            // own-h dependence first; below-layer wait hides inside the pipeline
            wait_ge(&g_prod[lay], 32u * (unsigned)t, tid);
            float acc[2][3][4] = {};
            gemm_run<0, 2>(g_hA[lay][rds], g_hA[lay - 1][wrs], 1024, 0,
                           wbase, pitchWB, sbuf, choff,
                           &g_prod[lay - 1], 32u * (unsigned)(t + 1), acc, tid, wg);
            if (tid == 0) atomicAdd(&g_cons[lay - 1], 1u);
            if (t >= RING) wait_ge(&g_cons[lay], consC * (unsigned)(t - 3), tid);
            const float* bl = bias + (long)lay * 1536;
            const float* bnl = b_n + (long)lay * 512;
            __half* slab = g_hA[lay][wrs];
            #pragma unroll
            for (int bs = 0; bs < 2; ++bs) {
                const int b = b0 + 8 * bs;
                float hh[2];
                #pragma unroll
                for (int d = 0; d < 2; ++d) {
                    const int g = g0 + d, idx = bs * 2 + d;
                    float ir = acc[1][0][idx] + __ldg(bl + g);
                    float iz = acc[1][1][idx] + __ldg(bl + 512 + g);
                    float in_ = acc[1][2][idx] + __ldg(bl + 1024 + g);
                    float r = sigm(ir + acc[0][0][idx]);
                    float z = sigm(iz + acc[0][1][idx]);
                    float n = tanhf(in_ + r * (acc[0][2][idx] + __ldg(bnl + g)));
                    float h = n + z * (hreg[idx] - n);
                    hreg[idx] = h; hh[d] = h;
                }
                __half2 hv; hv.x = __float2half(hh[0]); hv.y = __float2half(hh[1]);
                *(__half2*)(slab + (long)b * HH + g0) = hv;
            }
            __threadfence();
            __syncthreads();
            if (tid == 0) atomicAdd(&g_prod[lay], 1u);
        } else {
            wait_ge(&g_prod[2], 32u * (unsigned)(t + 1), tid);
            float acc[2][3][4] = {};
            if (wg == 0) {
                gemm_run<1, 1>(g_hA[2][wrs], g_hA[2][wrs], 0, 0,
                               wbase, pitchWB, sbuf, choff, 0, 0, acc, tid, wg);
                #pragma unroll
                for (int j = 0; j < 2; ++j) {
                    #pragma unroll
                    for (int bs = 0; bs < 2; ++bs) {
                        const int b = b0 + 8 * bs;
                        #pragma unroll
                        for (int d = 0; d < 2; ++d) {
                            int v = vbase + j * 8 + (lane & 3) * 2 + d;
                            if (v < 65)
                                out[((long)b * TT + t) * 65 + v] =
                                    acc[0][j][bs * 2 + d] + __ldg(b_out + v);
                        }
                    }
                }
            } else {
                gemm_run<2, 1>(g_hA[2][wrs], g_hA[2][wrs], 0, 0,
                               wbase, pitchWB, sbuf, choff, 0, 0, acc, tid, wg);
                #pragma unroll
                for (int bs = 0; bs < 2; ++bs) {
                    const int b = b0 + 8 * bs;
                    #pragma unroll
                    for (int d = 0; d < 2; ++d) {
                        int v = vbase + 16 + (lane & 3) * 2 + d;
                        if (v < 65)
                            out[((long)b * TT + t) * 65 + v] =
                                acc[0][2][bs * 2 + d] + __ldg(b_out + v);
                    }
                }
            }
            __syncthreads();
            if (tid == 0) atomicAdd(&g_cons[2], 1u);
        }
    }
}

// --------------------------------- launch ------------------------------------
extern "C" void kernel_launch(void* const* d_in, const int* in_sizes, int n_in,
                              void* d_out, int out_size) {
    const int*   x_seq = (const int*)  d_in[0];
    const float* emb   = (const float*)d_in[1];
    const float* w_ih  = (const float*)d_in[2];
    const float* w_hh  = (const float*)d_in[3];
    const float* b     = (const float*)d_in[4];
    const float* b_n   = (const float*)d_in[5];
    const float* w_out = (const float*)d_in[6];
    const float* b_out = (const float*)d_in[7];
    float* out = (float*)d_out;

    cudaFuncSetAttribute(k_main, cudaFuncAttributeMaxDynamicSharedMemorySize, SMEM_BYTES);

    k_zero<<<512, 256>>>();
    k_ig0<<<(65 * 1536 + 255) / 256, 256>>>(emb, w_ih, b);
    k_prepw<<<(int)((6L * 1536 * 512 + 255) / 256), 256>>>(w_ih, w_hh, w_out);
    k_main<<<NCTA, NTHR, SMEM_BYTES>>>(x_seq, b, b_n, b_out, out);
}